// round 5
// baseline (speedup 1.0000x reference)
#include <cuda_runtime.h>
#include <cstdint>

// 2x nearest-neighbor upsample via SMEM staging + TMA bulk stores.
//   in : (16, 64, 256, 256) fp32  -> (BC=1024, H=256, W=256)
//   out: (16, 64, 512, 512) fp32
//
// Per CTA (256 threads): 16 input rows -> 64 KB contiguous output span.
//   - float4 coalesced loads; width-duplicate into SMEM (16 rows x 2 KB).
//   - height duplication via TMA: 2 bulk stores per staged row, issued from
//     two warps (tid 0: rows 0-7, tid 128: rows 8-15), each its own group.

static constexpr int H_IN  = 256;
static constexpr int W_IN  = 256;
static constexpr int BC    = 16 * 64;   // 1024
static constexpr int ROWS  = 16;        // input rows per CTA
static constexpr int W_OUT = 512;
static constexpr int BLOCKS_PER_IMG = H_IN / ROWS;   // 16
static constexpr int GRID = BC * BLOCKS_PER_IMG;     // 16384
static constexpr int ROW_BYTES = W_OUT * 4;          // 2048

__global__ __launch_bounds__(256)
void upsample2x_tma_kernel(const float* __restrict__ in, float* __restrict__ out) {
    __shared__ alignas(128) float s[ROWS * W_OUT];   // 32 KB staged upsampled rows

    const int t   = blockIdx.x;
    const int bc  = t >> 4;                    // t / 16
    const int r0  = (t & 15) * ROWS;           // first input row of this tile
    const int tid = threadIdx.x;

    const float4* inp = (const float4*)(in + (long)bc * H_IN * W_IN + (long)r0 * W_IN);

    // 16 rows * 64 float4 = 1024 items; 4 per thread.
    #pragma unroll
    for (int it = 0; it < 4; ++it) {
        int k   = tid + it * 256;
        int row = k >> 6;       // 0..15
        int c4  = k & 63;       // float4 column within input row
        float4 v = __ldg(&inp[row * 64 + c4]);
        float4* d = (float4*)&s[row * W_OUT + 8 * c4];
        d[0] = make_float4(v.x, v.x, v.y, v.y);
        d[1] = make_float4(v.z, v.z, v.w, v.w);
    }

    // Order generic-proxy SMEM writes before async-proxy TMA reads.
    asm volatile("fence.proxy.async.shared::cta;" ::: "memory");
    __syncthreads();

    // Two issuing threads, each owns 8 staged rows (16 TMA stores), own group.
    if (tid == 0 || tid == 128) {
        const int rbeg = (tid == 0) ? 0 : 8;
        uint32_t sbase = (uint32_t)__cvta_generic_to_shared(s);
        float* obase = out + (long)bc * (2 * H_IN) * W_OUT + (long)(2 * r0) * W_OUT;
        #pragma unroll
        for (int r = rbeg; r < rbeg + 8; ++r) {
            uint32_t src = sbase + r * ROW_BYTES;
            float* d0 = obase + (long)(2 * r) * W_OUT;
            asm volatile("cp.async.bulk.global.shared::cta.bulk_group [%0], [%1], %2;"
                         :: "l"(d0), "r"(src), "r"(ROW_BYTES) : "memory");
            asm volatile("cp.async.bulk.global.shared::cta.bulk_group [%0], [%1], %2;"
                         :: "l"(d0 + W_OUT), "r"(src), "r"(ROW_BYTES) : "memory");
        }
        asm volatile("cp.async.bulk.commit_group;" ::: "memory");
        asm volatile("cp.async.bulk.wait_group 0;" ::: "memory");
    }
    // No thread may exit while TMA still reads this CTA's SMEM.
    __syncthreads();
}

extern "C" void kernel_launch(void* const* d_in, const int* in_sizes, int n_in,
                              void* d_out, int out_size) {
    (void)in_sizes; (void)n_in; (void)out_size;
    const float* in  = (const float*)d_in[0];
    float*       out = (float*)d_out;
    upsample2x_tma_kernel<<<GRID, 256>>>(in, out);
}

// round 6
// speedup vs baseline: 1.0134x; 1.0134x over previous
#include <cuda_runtime.h>
#include <cstdint>

// 2x nearest-neighbor upsample via SMEM staging + TMA bulk stores, with an
// intra-CTA pipeline: issue TMA for the first half of the tile while the
// second half is still being staged.
//   in : (16, 64, 256, 256) fp32  -> (BC=1024, H=256, W=256)
//   out: (16, 64, 512, 512) fp32
//
// Per CTA (256 threads): 8 input rows (16 KB staged).
//   phase A: stage rows 0-3 (float4 loads, width-dup to SMEM), sync
//   phase B: tid 0 issues 8 TMA stores (rows 0-3 -> out rows 0..7 of span)
//            while all threads stage rows 4-7, sync
//   phase C: tid 32 issues 8 TMA stores for rows 4-7; single wait.

static constexpr int H_IN  = 256;
static constexpr int W_IN  = 256;
static constexpr int BC    = 16 * 64;   // 1024
static constexpr int ROWS  = 8;
static constexpr int W_OUT = 512;
static constexpr int BLOCKS_PER_IMG = H_IN / ROWS;   // 32
static constexpr int GRID = BC * BLOCKS_PER_IMG;     // 32768
static constexpr int ROW_BYTES = W_OUT * 4;          // 2048

__device__ __forceinline__ void stage_half(const float4* __restrict__ inp,
                                           float* __restrict__ s,
                                           int tid, int half) {
    // 4 rows * 64 float4 = 256 items; 1 per thread.
    int k   = tid;
    int row = half * 4 + (k >> 6);   // 4 rows per half
    int c4  = k & 63;
    float4 v = __ldg(&inp[row * 64 + c4]);
    float4* d = (float4*)&s[row * W_OUT + 8 * c4];
    d[0] = make_float4(v.x, v.x, v.y, v.y);
    d[1] = make_float4(v.z, v.z, v.w, v.w);
}

__device__ __forceinline__ void issue_half(uint32_t sbase, float* obase, int rbeg) {
    #pragma unroll
    for (int r = rbeg; r < rbeg + 4; ++r) {
        uint32_t src = sbase + r * ROW_BYTES;
        float* d0 = obase + (long)(2 * r) * W_OUT;
        asm volatile("cp.async.bulk.global.shared::cta.bulk_group [%0], [%1], %2;"
                     :: "l"(d0), "r"(src), "r"(ROW_BYTES) : "memory");
        asm volatile("cp.async.bulk.global.shared::cta.bulk_group [%0], [%1], %2;"
                     :: "l"(d0 + W_OUT), "r"(src), "r"(ROW_BYTES) : "memory");
    }
}

__global__ __launch_bounds__(256)
void upsample2x_tma_kernel(const float* __restrict__ in, float* __restrict__ out) {
    __shared__ alignas(128) float s[ROWS * W_OUT];   // 16 KB

    const int t   = blockIdx.x;
    const int bc  = t >> 5;            // t / 32
    const int r0  = (t & 31) * ROWS;   // first input row of this tile
    const int tid = threadIdx.x;

    const float4* inp = (const float4*)(in + (long)bc * H_IN * W_IN + (long)r0 * W_IN);
    float* obase = out + (long)bc * (2 * H_IN) * W_OUT + (long)(2 * r0) * W_OUT;
    uint32_t sbase = (uint32_t)__cvta_generic_to_shared(s);

    // Phase A: stage rows 0-3
    stage_half(inp, s, tid, 0);
    asm volatile("fence.proxy.async.shared::cta;" ::: "memory");
    __syncthreads();

    // Phase B: issue first half, overlap with staging rows 4-7
    if (tid == 0) issue_half(sbase, obase, 0);
    stage_half(inp, s, tid, 1);
    asm volatile("fence.proxy.async.shared::cta;" ::: "memory");
    __syncthreads();

    // Phase C: issue second half, then drain both halves.
    if (tid == 32) issue_half(sbase, obase, 4);

    if (tid == 0 || tid == 32) {
        asm volatile("cp.async.bulk.commit_group;" ::: "memory");
        asm volatile("cp.async.bulk.wait_group 0;" ::: "memory");
    }
    // No thread may exit while TMA still reads this CTA's SMEM.
    __syncthreads();
}

extern "C" void kernel_launch(void* const* d_in, const int* in_sizes, int n_in,
                              void* d_out, int out_size) {
    (void)in_sizes; (void)n_in; (void)out_size;
    const float* in  = (const float*)d_in[0];
    float*       out = (float*)d_out;
    upsample2x_tma_kernel<<<GRID, 256>>>(in, out);
}

// round 8
// speedup vs baseline: 1.0150x; 1.0016x over previous
#include <cuda_runtime.h>
#include <cstdint>

// 2x nearest-neighbor upsample: stage the FULLY upsampled tile (width AND
// height duplicated) in SMEM so each half-tile is one contiguous 16 KB
// cp.async.bulk store. Pipelined: issue half 1 while staging half 2.
//   in : (16, 64, 256, 256) fp32  -> (BC=1024, H=256, W=256)
//   out: (16, 64, 512, 512) fp32
//
// Per CTA (256 threads): 8 input rows -> 16 output rows (32 KB staged).

static constexpr int H_IN  = 256;
static constexpr int W_IN  = 256;
static constexpr int BC    = 16 * 64;   // 1024
static constexpr int ROWS  = 8;         // input rows per CTA
static constexpr int W_OUT = 512;
static constexpr int BLOCKS_PER_IMG = H_IN / ROWS;   // 32
static constexpr int GRID = BC * BLOCKS_PER_IMG;     // 32768
static constexpr int HALF_BYTES = 8 * W_OUT * 4;     // 8 output rows = 16384 B

__device__ __forceinline__ void stage_half(const float4* __restrict__ inp,
                                           float* __restrict__ s,
                                           int tid, int half) {
    // 4 input rows * 64 float4 = 256 items; 1 per thread.
    // Each item produces 2 width-dup float4s, written to BOTH smem rows 2r, 2r+1.
    int row = half * 4 + (tid >> 6);   // input row 0..7
    int c4  = tid & 63;
    float4 v = __ldg(&inp[row * 64 + c4]);
    float4 lo = make_float4(v.x, v.x, v.y, v.y);
    float4 hi = make_float4(v.z, v.z, v.w, v.w);
    float4* d0 = (float4*)&s[(2 * row) * W_OUT + 8 * c4];
    float4* d1 = (float4*)&s[(2 * row + 1) * W_OUT + 8 * c4];
    d0[0] = lo; d0[1] = hi;
    d1[0] = lo; d1[1] = hi;
}

__global__ __launch_bounds__(256)
void upsample2x_tma_kernel(const float* __restrict__ in, float* __restrict__ out) {
    __shared__ alignas(128) float s[2 * ROWS * W_OUT];   // 32 KB: full upsampled tile

    const int t   = blockIdx.x;
    const int bc  = t >> 5;            // t / 32
    const int r0  = (t & 31) * ROWS;   // first input row of this tile
    const int tid = threadIdx.x;

    const float4* inp = (const float4*)(in + (long)bc * H_IN * W_IN + (long)r0 * W_IN);
    float* obase = out + (long)bc * (2 * H_IN) * W_OUT + (long)(2 * r0) * W_OUT;
    uint32_t sbase = (uint32_t)__cvta_generic_to_shared(s);

    // Phase A: stage input rows 0-3 -> smem out rows 0-7 (16 KB)
    stage_half(inp, s, tid, 0);
    asm volatile("fence.proxy.async.shared::cta;" ::: "memory");
    __syncthreads();

    // Phase B: issue first 16 KB bulk store; overlap staging rows 4-7
    if (tid == 0) {
        asm volatile("cp.async.bulk.global.shared::cta.bulk_group [%0], [%1], %2;"
                     :: "l"(obase), "r"(sbase), "n"(HALF_BYTES) : "memory");
    }
    stage_half(inp, s, tid, 1);
    asm volatile("fence.proxy.async.shared::cta;" ::: "memory");
    __syncthreads();

    // Phase C: issue second 16 KB bulk store; drain both.
    if (tid == 32) {
        asm volatile("cp.async.bulk.global.shared::cta.bulk_group [%0], [%1], %2;"
                     :: "l"(obase + 8 * W_OUT), "r"(sbase + HALF_BYTES), "n"(HALF_BYTES)
                     : "memory");
    }
    if (tid == 0 || tid == 32) {
        asm volatile("cp.async.bulk.commit_group;" ::: "memory");
        asm volatile("cp.async.bulk.wait_group 0;" ::: "memory");
    }
    // No thread may exit while TMA still reads this CTA's SMEM.
    __syncthreads();
}

extern "C" void kernel_launch(void* const* d_in, const int* in_sizes, int n_in,
                              void* d_out, int out_size) {
    (void)in_sizes; (void)n_in; (void)out_size;
    const float* in  = (const float*)d_in[0];
    float*       out = (float*)d_out;
    upsample2x_tma_kernel<<<GRID, 256>>>(in, out);
}